// round 3
// baseline (speedup 1.0000x reference)
#include <cuda_runtime.h>
#include <math.h>

// Router: patch (N=32768, C=32, H=8, W=8) f32, keys (16,32) f32, 3 scalars.
// Output: weights_filtered (N, 16) f32.
//
// One warp per patch. Fully-coalesced float4 streaming loads, shfl butterfly
// channel reduction, smem-staged keys, rank-based top-k stats.

#define WARPS_PER_BLOCK 8
#define THREADS (WARPS_PER_BLOCK * 32)
#define EXPERTS 16
#define CHANNELS 32
#define PATCH_F4 512   // 32*64 floats / 4

__global__ __launch_bounds__(THREADS) void router_kernel(
    const float* __restrict__ patch,
    const float* __restrict__ keys,
    const float* __restrict__ temp_p,
    const float* __restrict__ beta_p,
    const float* __restrict__ thr_p,
    float* __restrict__ out,
    int n_patches)
{
    __shared__ float keys_s[EXPERTS * 33];            // padded: bank-conflict-free
    __shared__ float scratch[WARPS_PER_BLOCK][32];    // emb, then [0:16)=weights, [16:32)=sorted

    const int tid  = threadIdx.x;
    const int wid  = tid >> 5;
    const int lane = tid & 31;

    // Stage keys into padded smem
    for (int i = tid; i < EXPERTS * CHANNELS; i += THREADS) {
        int e = i >> 5, c = i & 31;
        keys_s[e * 33 + c] = keys[i];
    }
    __syncthreads();

    const int patch_id = blockIdx.x * WARPS_PER_BLOCK + wid;
    if (patch_id >= n_patches) return;

    const float inv_temp = 1.0f / (*temp_p);
    const float beta     = (*beta_p) + 1e-8f;
    const float thr      = *thr_p;

    // ---- Coalesced streaming load: 16 x float4 per lane (512 f4 per patch).
    // float4 index f = i*32+lane covers channel 2i + (lane>>4).
    // Collapse each float4 to a scalar immediately: keeps 16-deep LDG MLP
    // while capping register pressure.
    const float4* p4 = reinterpret_cast<const float4*>(patch) + (size_t)patch_id * PATCH_F4;
    float s[16];
#pragma unroll
    for (int i = 0; i < 16; i++) {
        float4 t = __ldcs(&p4[i * 32 + lane]);
        s[i] = (t.x + t.y) + (t.z + t.w);
    }

    // ---- Butterfly reduce each 16-lane half; lane 0 / lane 16 hold channel sums.
#pragma unroll
    for (int i = 0; i < 16; i++) {
        float r = s[i];
        r += __shfl_xor_sync(0xFFFFFFFFu, r, 1);
        r += __shfl_xor_sync(0xFFFFFFFFu, r, 2);
        r += __shfl_xor_sync(0xFFFFFFFFu, r, 4);
        r += __shfl_xor_sync(0xFFFFFFFFu, r, 8);
        if ((lane & 15) == 0) scratch[wid][2 * i + (lane >> 4)] = r;
    }
    __syncwarp();

    // ---- Normalize embedding (lane c holds emb[c]) ----
    float emb = scratch[wid][lane] * (1.0f / 64.0f);
    float sq = emb * emb;
#pragma unroll
    for (int k = 16; k; k >>= 1) sq += __shfl_xor_sync(0xFFFFFFFFu, sq, k);
    float nrm = fmaxf(sqrtf(sq), 1e-12f);
    float en = emb / nrm;
    scratch[wid][lane] = en;
    __syncwarp();

    // ---- Logits: lane e (<16) computes dot over 32 channels ----
    float logit = 0.0f;
    if (lane < EXPERTS) {
        const float* kr = &keys_s[lane * 33];
#pragma unroll
        for (int c = 0; c < CHANNELS; c++)
            logit = fmaf(scratch[wid][c], kr[c], logit);
    }
    __syncwarp();

    float sl = logit * inv_temp + 1e-8f;

    // ---- Softmax over 16 lanes (xor masks 1,2,4,8 stay within half-warp) ----
    float m = sl;
#pragma unroll
    for (int k = 8; k; k >>= 1) m = fmaxf(m, __shfl_xor_sync(0xFFFFFFFFu, m, k));
    float ew = expf(sl - m);
    float denom = ew;
#pragma unroll
    for (int k = 8; k; k >>= 1) denom += __shfl_xor_sync(0xFFFFFFFFu, denom, k);
    float w = ew / denom;

    // ---- Moments / entropy over the 16 weights ----
    float sw   = w;
    float swsq = w * w;
    float swl  = w * logf(w + 1e-18f);
#pragma unroll
    for (int k = 8; k; k >>= 1) {
        sw   += __shfl_xor_sync(0xFFFFFFFFu, sw,   k);
        swsq += __shfl_xor_sync(0xFFFFFFFFu, swsq, k);
        swl  += __shfl_xor_sync(0xFFFFFFFFu, swl,  k);
    }

    // ---- Descending sort via rank (stable tie-break by index) ----
    if (lane < EXPERTS) scratch[wid][lane] = w;     // weights in [0:16)
    __syncwarp();
    if (lane < EXPERTS) {
        int rank = 0;
#pragma unroll
        for (int j = 0; j < EXPERTS; j++) {
            float wj = scratch[wid][j];
            rank += (wj > w) || (wj == w && j < lane);
        }
        scratch[wid][16 + rank] = w;                // sorted in [16:32)
    }
    __syncwarp();

    const float s0 = scratch[wid][16 + 0];
    const float s1 = scratch[wid][16 + 1];
    const float s2 = scratch[wid][16 + 2];
    const float s3 = scratch[wid][16 + 3];
    const float s4 = scratch[wid][16 + 4];

    // ---- Adaptive threshold ----
    const float mean    = sw * (1.0f / 16.0f);
    const float var     = fmaxf(0.0f, (swsq - sw * sw * (1.0f / 16.0f)) * (1.0f / 15.0f));
    const float stdw    = sqrtf(var);
    const float entropy = -swl;

    const float max_comp = 1.0f - s0;
    const float ent_comp = 1.0f - entropy * 0.360673760222f;  // 1/ln(16)
    const float mean_rest = (s1 + s2 + s3 + s4) * 0.25f;
    float gap = (s0 - mean_rest) / (s0 + 1e-8f);
    gap = fminf(fmaxf(gap, 0.0f), 1.0f);

    float adaptive = thr * (0.5f + 0.4f * max_comp + 0.3f * ent_comp + 0.3f * gap);
    const float min_thr = fmaxf(0.05f, mean - 0.5f * stdw);
    const float max_thr = fminf(0.7f, s0 - 0.1f * stdw);
    adaptive = fminf(fmaxf(adaptive, min_thr), max_thr);
    adaptive = fminf(adaptive, s3 * 0.9f);          // kth = sorted[MIN_EXPERTS_ACTIVE-1]

    // ---- Soft mask, filter, renormalize ----
    const float mask = 1.0f / (1.0f + expf(-beta * (w - adaptive)));
    float wf = w * mask;
    float swf = wf;
#pragma unroll
    for (int k = 8; k; k >>= 1) swf += __shfl_xor_sync(0xFFFFFFFFu, swf, k);
    const float o = wf / fmaxf(swf, 1e-8f);

    if (lane < EXPERTS)
        out[(size_t)patch_id * EXPERTS + lane] = o;
}

extern "C" void kernel_launch(void* const* d_in, const int* in_sizes, int n_in,
                              void* d_out, int out_size)
{
    const float* patch  = (const float*)d_in[0];
    const float* keys   = (const float*)d_in[1];
    const float* temp_p = (const float*)d_in[2];
    const float* beta_p = (const float*)d_in[3];
    const float* thr_p  = (const float*)d_in[4];
    float* out = (float*)d_out;

    const int n_patches = in_sizes[0] / (CHANNELS * 64);   // 32768
    const int blocks = (n_patches + WARPS_PER_BLOCK - 1) / WARPS_PER_BLOCK;

    router_kernel<<<blocks, THREADS>>>(patch, keys, temp_p, beta_p, thr_p, out, n_patches);
}

// round 5
// speedup vs baseline: 1.0406x; 1.0406x over previous
#include <cuda_runtime.h>
#include <math.h>

// Router: patch (N=32768, C=32, H=8, W=8) f32, keys (16,32) f32, 3 scalars.
// Output: weights_filtered (N, 16) f32.
//
// One warp per patch. Coalesced float4 streaming loads; 15-shfl
// recursive-halving channel reduction; smem-staged keys; rank-based sort.

#define WARPS_PER_BLOCK 8
#define THREADS (WARPS_PER_BLOCK * 32)
#define EXPERTS 16
#define CHANNELS 32
#define PATCH_F4 512   // 32*64 floats / 4

__global__ __launch_bounds__(THREADS, 8) void router_kernel(
    const float* __restrict__ patch,
    const float* __restrict__ keys,
    const float* __restrict__ temp_p,
    const float* __restrict__ beta_p,
    const float* __restrict__ thr_p,
    float* __restrict__ out,
    int n_patches)
{
    __shared__ float keys_s[EXPERTS * 33];            // padded rows
    __shared__ float scratch[WARPS_PER_BLOCK][32];    // emb, weights, sorted

    const int tid  = threadIdx.x;
    const int wid  = tid >> 5;
    const int lane = tid & 31;

    for (int i = tid; i < EXPERTS * CHANNELS; i += THREADS) {
        int e = i >> 5, c = i & 31;
        keys_s[e * 33 + c] = keys[i];
    }
    __syncthreads();

    const int patch_id = blockIdx.x * WARPS_PER_BLOCK + wid;
    if (patch_id >= n_patches) return;

    const float inv_temp = 1.0f / (*temp_p);
    const float beta     = (*beta_p) + 1e-8f;
    const float thr      = *thr_p;

    // ---- Coalesced streaming load. float4 f = i*32+lane covers channel
    // 2i + (lane>>4), spatial (lane&15)*4. Collapse to scalar immediately.
    const float4* p4 = reinterpret_cast<const float4*>(patch) + (size_t)patch_id * PATCH_F4;
    float s[16];
#pragma unroll
    for (int i = 0; i < 16; i++) {
        float4 t = __ldcs(&p4[i * 32 + lane]);
        s[i] = (t.x + t.y) + (t.z + t.w);
    }

    // ---- Recursive-halving exchange: 15 shfls total. Each stage k swaps
    // half the values with lane^k and compacts. Lane ends holding the full
    // 16-lane sum of value index m = lane&15 (masks <16 stay in-half).
    const int m = lane & 15;
    float t8[8];
    {
        const bool up = (m & 8);
#pragma unroll
        for (int i = 0; i < 8; i++) {
            float send = up ? s[i] : s[i + 8];
            float r = __shfl_xor_sync(0xFFFFFFFFu, send, 8);
            t8[i] = (up ? s[i + 8] : s[i]) + r;
        }
    }
    float t4[4];
    {
        const bool up = (m & 4);
#pragma unroll
        for (int i = 0; i < 4; i++) {
            float send = up ? t8[i] : t8[i + 4];
            float r = __shfl_xor_sync(0xFFFFFFFFu, send, 4);
            t4[i] = (up ? t8[i + 4] : t8[i]) + r;
        }
    }
    float t2[2];
    {
        const bool up = (m & 2);
#pragma unroll
        for (int i = 0; i < 2; i++) {
            float send = up ? t2[0] : t2[0];  // placeholder, replaced below
            (void)send;
            float snd = up ? t4[i] : t4[i + 2];
            float r = __shfl_xor_sync(0xFFFFFFFFu, snd, 2);
            t2[i] = (up ? t4[i + 2] : t4[i]) + r;
        }
    }
    float chansum;
    {
        const bool up = (m & 1);
        float snd = up ? t2[0] : t2[1];
        float r = __shfl_xor_sync(0xFFFFFFFFu, snd, 1);
        chansum = (up ? t2[1] : t2[0]) + r;
    }
    // chansum at lane l = sum for channel 2*(l&15) + (l>>4).
    // Permute so lane c holds channel c: source lane = ((c&1)<<4) | (c>>1).
    const int src = ((lane & 1) << 4) | (lane >> 1);
    float emb = __shfl_sync(0xFFFFFFFFu, chansum, src) * (1.0f / 64.0f);

    // ---- Normalize ----
    float sq = emb * emb;
#pragma unroll
    for (int k = 16; k; k >>= 1) sq += __shfl_xor_sync(0xFFFFFFFFu, sq, k);
    float en = emb / fmaxf(sqrtf(sq), 1e-12f);
    scratch[wid][lane] = en;
    __syncwarp();

    // ---- Logits: lane e (<16) dot over 32 channels ----
    float logit = 0.0f;
    if (lane < EXPERTS) {
        const float* kr = &keys_s[lane * 33];
#pragma unroll
        for (int c = 0; c < CHANNELS; c++)
            logit = fmaf(scratch[wid][c], kr[c], logit);
    }
    __syncwarp();

    float sl = logit * inv_temp + 1e-8f;

    // ---- Softmax over 16 lanes ----
    float mx = sl;
#pragma unroll
    for (int k = 8; k; k >>= 1) mx = fmaxf(mx, __shfl_xor_sync(0xFFFFFFFFu, mx, k));
    float ew = __expf(sl - mx);
    float denom = ew;
#pragma unroll
    for (int k = 8; k; k >>= 1) denom += __shfl_xor_sync(0xFFFFFFFFu, denom, k);
    float w = ew / denom;

    // ---- Moments / entropy ----
    float sw   = w;
    float swsq = w * w;
    float swl  = w * __logf(w + 1e-18f);
#pragma unroll
    for (int k = 8; k; k >>= 1) {
        sw   += __shfl_xor_sync(0xFFFFFFFFu, sw,   k);
        swsq += __shfl_xor_sync(0xFFFFFFFFu, swsq, k);
        swl  += __shfl_xor_sync(0xFFFFFFFFu, swl,  k);
    }

    // ---- Descending sort via rank (stable tie-break by index) ----
    if (lane < EXPERTS) scratch[wid][lane] = w;
    __syncwarp();
    if (lane < EXPERTS) {
        int rank = 0;
#pragma unroll
        for (int j = 0; j < EXPERTS; j++) {
            float wj = scratch[wid][j];
            rank += (wj > w) || (wj == w && j < lane);
        }
        scratch[wid][16 + rank] = w;
    }
    __syncwarp();

    const float s0 = scratch[wid][16 + 0];
    const float s1 = scratch[wid][16 + 1];
    const float s2 = scratch[wid][16 + 2];
    const float s3 = scratch[wid][16 + 3];
    const float s4 = scratch[wid][16 + 4];

    // ---- Adaptive threshold ----
    const float mean    = sw * (1.0f / 16.0f);
    const float var     = fmaxf(0.0f, (swsq - sw * sw * (1.0f / 16.0f)) * (1.0f / 15.0f));
    const float stdw    = sqrtf(var);
    const float entropy = -swl;

    const float max_comp = 1.0f - s0;
    const float ent_comp = 1.0f - entropy * 0.360673760222f;  // 1/ln(16)
    const float mean_rest = (s1 + s2 + s3 + s4) * 0.25f;
    float gap = (s0 - mean_rest) / (s0 + 1e-8f);
    gap = fminf(fmaxf(gap, 0.0f), 1.0f);

    float adaptive = thr * (0.5f + 0.4f * max_comp + 0.3f * ent_comp + 0.3f * gap);
    const float min_thr = fmaxf(0.05f, mean - 0.5f * stdw);
    const float max_thr = fminf(0.7f, s0 - 0.1f * stdw);
    adaptive = fminf(fmaxf(adaptive, min_thr), max_thr);
    adaptive = fminf(adaptive, s3 * 0.9f);

    // ---- Soft mask, filter, renormalize ----
    const float mask = 1.0f / (1.0f + __expf(-beta * (w - adaptive)));
    float wf = w * mask;
    float swf = wf;
#pragma unroll
    for (int k = 8; k; k >>= 1) swf += __shfl_xor_sync(0xFFFFFFFFu, swf, k);
    const float o = wf / fmaxf(swf, 1e-8f);

    if (lane < EXPERTS)
        out[(size_t)patch_id * EXPERTS + lane] = o;
}

extern "C" void kernel_launch(void* const* d_in, const int* in_sizes, int n_in,
                              void* d_out, int out_size)
{
    const float* patch  = (const float*)d_in[0];
    const float* keys   = (const float*)d_in[1];
    const float* temp_p = (const float*)d_in[2];
    const float* beta_p = (const float*)d_in[3];
    const float* thr_p  = (const float*)d_in[4];
    float* out = (float*)d_out;

    const int n_patches = in_sizes[0] / (CHANNELS * 64);   // 32768
    const int blocks = (n_patches + WARPS_PER_BLOCK - 1) / WARPS_PER_BLOCK;

    router_kernel<<<blocks, THREADS>>>(patch, keys, temp_p, beta_p, thr_p, out, n_patches);
}

// round 6
// speedup vs baseline: 1.0413x; 1.0006x over previous
#include <cuda_runtime.h>
#include <math.h>

// Router: patch (N=32768, C=32, H=8, W=8) f32, keys (16,32) f32, 3 scalars.
// Output: weights_filtered (N, 16) f32.
//
// Persistent single-wave grid: 1024 CTAs x 8 warps, each warp strides over
// 4 patches. Coalesced float4 streaming loads; 15-shfl recursive-halving
// channel reduction; smem-staged keys; rank-based sort.

#define WARPS_PER_BLOCK 8
#define THREADS (WARPS_PER_BLOCK * 32)
#define GRID_BLOCKS 1024
#define EXPERTS 16
#define CHANNELS 32
#define PATCH_F4 512   // 32*64 floats / 4

__global__ __launch_bounds__(THREADS, 8) void router_kernel(
    const float* __restrict__ patch,
    const float* __restrict__ keys,
    const float* __restrict__ temp_p,
    const float* __restrict__ beta_p,
    const float* __restrict__ thr_p,
    float* __restrict__ out,
    int n_patches)
{
    __shared__ float keys_s[EXPERTS * 33];            // padded rows
    __shared__ float scratch[WARPS_PER_BLOCK][32];    // emb, weights, sorted

    const int tid  = threadIdx.x;
    const int wid  = tid >> 5;
    const int lane = tid & 31;

    for (int i = tid; i < EXPERTS * CHANNELS; i += THREADS) {
        int e = i >> 5, c = i & 31;
        keys_s[e * 33 + c] = keys[i];
    }

    // Loop-invariant scalars (loaded once per warp, before the patch loop)
    const float inv_temp = 1.0f / (*temp_p);
    const float beta     = (*beta_p) + 1e-8f;
    const float thr      = *thr_p;
    __syncthreads();

    const int warp_global  = blockIdx.x * WARPS_PER_BLOCK + wid;
    const int total_warps  = gridDim.x * WARPS_PER_BLOCK;
    const int m   = lane & 15;
    const int src = ((lane & 1) << 4) | (lane >> 1);  // inverse channel permutation

    for (int patch_id = warp_global; patch_id < n_patches; patch_id += total_warps) {

        // ---- Coalesced streaming load. float4 f = i*32+lane covers channel
        // 2i + (lane>>4), spatial (lane&15)*4. Collapse to scalar immediately.
        const float4* p4 = reinterpret_cast<const float4*>(patch) + (size_t)patch_id * PATCH_F4;
        float s[16];
#pragma unroll
        for (int i = 0; i < 16; i++) {
            float4 t = __ldcs(&p4[i * 32 + lane]);
            s[i] = (t.x + t.y) + (t.z + t.w);
        }

        // ---- Recursive-halving exchange: 15 shfls. Lane ends holding the
        // 16-lane sum of value index (lane&15) => channel 2*(lane&15)+(lane>>4).
        float t8[8];
        {
            const bool up = (m & 8);
#pragma unroll
            for (int i = 0; i < 8; i++) {
                float snd = up ? s[i] : s[i + 8];
                float r = __shfl_xor_sync(0xFFFFFFFFu, snd, 8);
                t8[i] = (up ? s[i + 8] : s[i]) + r;
            }
        }
        float t4[4];
        {
            const bool up = (m & 4);
#pragma unroll
            for (int i = 0; i < 4; i++) {
                float snd = up ? t8[i] : t8[i + 4];
                float r = __shfl_xor_sync(0xFFFFFFFFu, snd, 4);
                t4[i] = (up ? t8[i + 4] : t8[i]) + r;
            }
        }
        float t2[2];
        {
            const bool up = (m & 2);
#pragma unroll
            for (int i = 0; i < 2; i++) {
                float snd = up ? t4[i] : t4[i + 2];
                float r = __shfl_xor_sync(0xFFFFFFFFu, snd, 2);
                t2[i] = (up ? t4[i + 2] : t4[i]) + r;
            }
        }
        float chansum;
        {
            const bool up = (m & 1);
            float snd = up ? t2[0] : t2[1];
            float r = __shfl_xor_sync(0xFFFFFFFFu, snd, 1);
            chansum = (up ? t2[1] : t2[0]) + r;
        }
        // Permute so lane c holds channel c's mean.
        float emb = __shfl_sync(0xFFFFFFFFu, chansum, src) * (1.0f / 64.0f);

        // ---- Normalize ----
        float sq = emb * emb;
#pragma unroll
        for (int k = 16; k; k >>= 1) sq += __shfl_xor_sync(0xFFFFFFFFu, sq, k);
        float en = emb / fmaxf(sqrtf(sq), 1e-12f);
        scratch[wid][lane] = en;
        __syncwarp();

        // ---- Logits: lane e (<16) dot over 32 channels ----
        float logit = 0.0f;
        if (lane < EXPERTS) {
            const float* kr = &keys_s[lane * 33];
#pragma unroll
            for (int c = 0; c < CHANNELS; c++)
                logit = fmaf(scratch[wid][c], kr[c], logit);
        }
        __syncwarp();

        float sl = logit * inv_temp + 1e-8f;

        // ---- Softmax over 16 lanes ----
        float mx = sl;
#pragma unroll
        for (int k = 8; k; k >>= 1) mx = fmaxf(mx, __shfl_xor_sync(0xFFFFFFFFu, mx, k));
        float ew = __expf(sl - mx);
        float denom = ew;
#pragma unroll
        for (int k = 8; k; k >>= 1) denom += __shfl_xor_sync(0xFFFFFFFFu, denom, k);
        float w = ew / denom;

        // ---- Moments / entropy ----
        float sw   = w;
        float swsq = w * w;
        float swl  = w * __logf(w + 1e-18f);
#pragma unroll
        for (int k = 8; k; k >>= 1) {
            sw   += __shfl_xor_sync(0xFFFFFFFFu, sw,   k);
            swsq += __shfl_xor_sync(0xFFFFFFFFu, swsq, k);
            swl  += __shfl_xor_sync(0xFFFFFFFFu, swl,  k);
        }

        // ---- Descending sort via rank (stable tie-break by index) ----
        if (lane < EXPERTS) scratch[wid][lane] = w;
        __syncwarp();
        if (lane < EXPERTS) {
            int rank = 0;
#pragma unroll
            for (int j = 0; j < EXPERTS; j++) {
                float wj = scratch[wid][j];
                rank += (wj > w) || (wj == w && j < lane);
            }
            scratch[wid][16 + rank] = w;
        }
        __syncwarp();

        const float s0 = scratch[wid][16 + 0];
        const float s1 = scratch[wid][16 + 1];
        const float s2 = scratch[wid][16 + 2];
        const float s3 = scratch[wid][16 + 3];
        const float s4 = scratch[wid][16 + 4];
        __syncwarp();   // sorted values consumed before next iter overwrites

        // ---- Adaptive threshold ----
        const float mean    = sw * (1.0f / 16.0f);
        const float var     = fmaxf(0.0f, (swsq - sw * sw * (1.0f / 16.0f)) * (1.0f / 15.0f));
        const float stdw    = sqrtf(var);
        const float entropy = -swl;

        const float max_comp = 1.0f - s0;
        const float ent_comp = 1.0f - entropy * 0.360673760222f;  // 1/ln(16)
        const float mean_rest = (s1 + s2 + s3 + s4) * 0.25f;
        float gap = (s0 - mean_rest) / (s0 + 1e-8f);
        gap = fminf(fmaxf(gap, 0.0f), 1.0f);

        float adaptive = thr * (0.5f + 0.4f * max_comp + 0.3f * ent_comp + 0.3f * gap);
        const float min_thr = fmaxf(0.05f, mean - 0.5f * stdw);
        const float max_thr = fminf(0.7f, s0 - 0.1f * stdw);
        adaptive = fminf(fmaxf(adaptive, min_thr), max_thr);
        adaptive = fminf(adaptive, s3 * 0.9f);

        // ---- Soft mask, filter, renormalize ----
        const float mask = 1.0f / (1.0f + __expf(-beta * (w - adaptive)));
        float wf = w * mask;
        float swf = wf;
#pragma unroll
        for (int k = 8; k; k >>= 1) swf += __shfl_xor_sync(0xFFFFFFFFu, swf, k);
        const float o = wf / fmaxf(swf, 1e-8f);

        if (lane < EXPERTS)
            out[(size_t)patch_id * EXPERTS + lane] = o;
    }
}

extern "C" void kernel_launch(void* const* d_in, const int* in_sizes, int n_in,
                              void* d_out, int out_size)
{
    const float* patch  = (const float*)d_in[0];
    const float* keys   = (const float*)d_in[1];
    const float* temp_p = (const float*)d_in[2];
    const float* beta_p = (const float*)d_in[3];
    const float* thr_p  = (const float*)d_in[4];
    float* out = (float*)d_out;

    const int n_patches = in_sizes[0] / (CHANNELS * 64);   // 32768
    int blocks = GRID_BLOCKS;
    int needed = (n_patches + WARPS_PER_BLOCK - 1) / WARPS_PER_BLOCK;
    if (needed < blocks) blocks = needed;

    router_kernel<<<blocks, THREADS>>>(patch, keys, temp_p, beta_p, thr_p, out, n_patches);
}